// round 1
// baseline (speedup 1.0000x reference)
#include <cuda_runtime.h>
#include <math.h>

// Problem constants: B=2, S=512 -> TT=1024 tokens, H=1024, I=512, E=64, K=8
#define TT 1024
#define HH 1024
#define II 512
#define EE 64
#define KK 8

#define BM 64
#define BN 64
#define BK 16

// ---------------- device scratch (static globals; no allocation allowed) ----
__device__ int   g_top_idx[TT * KK];
__device__ float g_top_w[TT * KK];
__device__ int   g_count[EE];
__device__ int   g_off[EE + 1];
__device__ int   g_tok[TT * KK];
__device__ float g_w[TT * KK];
__device__ float g_shared_act[TT * II];           // 2 MB
__device__ float g_routed_act[TT * KK * II];      // 16 MB

// ---------------- phase 0: zero per-expert counters ------------------------
__global__ void k_zero() {
    if (threadIdx.x < EE) g_count[threadIdx.x] = 0;
}

// ---------------- phase 1: router (logits -> sigmoid -> top-8) --------------
// one block (256 thr) per token
__global__ void k_router(const float* __restrict__ X, const float* __restrict__ Wr) {
    __shared__ float xs[HH];
    __shared__ float part[4][EE];
    __shared__ float aff[EE];
    const int t = blockIdx.x;
    for (int i = threadIdx.x; i < HH; i += 256) xs[i] = X[(size_t)t * HH + i];
    __syncthreads();

    const int e = threadIdx.x & 63;   // expert
    const int q = threadIdx.x >> 6;   // quarter of H
    float p = 0.f;
    for (int h = q; h < HH; h += 4) p += xs[h] * Wr[h * EE + e];
    part[q][e] = p;
    __syncthreads();

    if (threadIdx.x < EE) {
        float s = part[0][e] + part[1][e] + part[2][e] + part[3][e];
        aff[e] = 1.f / (1.f + expf(-s));
    }
    __syncthreads();

    if (threadIdx.x == 0) {
        float sum = 0.f;
        int   bi[KK];
        float bv[KK];
        #pragma unroll
        for (int k = 0; k < KK; k++) {
            int best = 0; float bvv = -1.f;
            for (int ee = 0; ee < EE; ee++) {
                float v = aff[ee];
                if (v > bvv) { bvv = v; best = ee; }
            }
            bi[k] = best; bv[k] = bvv;
            aff[best] = -1.f;
            sum += bvv;
        }
        const float inv = 1.f / (sum + 1e-9f);
        #pragma unroll
        for (int k = 0; k < KK; k++) {
            g_top_idx[t * KK + k] = bi[k];
            g_top_w[t * KK + k]   = bv[k] * inv;
            atomicAdd(&g_count[bi[k]], 1);
        }
    }
}

// ---------------- phase 2: exclusive scan of counts -------------------------
__global__ void k_scan() {
    if (threadIdx.x == 0) {
        int run = 0;
        for (int e = 0; e < EE; e++) {
            g_off[e] = run;
            run += g_count[e];
            g_count[e] = 0;          // reused as fill cursor in k_assign
        }
        g_off[EE] = run;             // == TT*KK == 8192
    }
}

// ---------------- phase 3: compact per-expert token/weight lists -------------
__global__ void k_assign() {
    const int t = blockIdx.x * blockDim.x + threadIdx.x;
    if (t >= TT) return;
    #pragma unroll
    for (int k = 0; k < KK; k++) {
        const int e    = g_top_idx[t * KK + k];
        const int slot = atomicAdd(&g_count[e], 1);
        const int pos  = g_off[e] + slot;
        g_tok[pos] = t;
        g_w[pos]   = g_top_w[t * KK + k];
    }
}

// ---------------- fused gate+up SwiGLU GEMM ---------------------------------
// C[m, n] = silu(A@Wg)[m,n] * (A@Wu)[m,n] * (row weight if GATHER)
// A: [*, HH] row-major (gathered rows if GATHER). Wg/Wu: [HH, II] row-major.
template <bool GATHER>
__global__ void k_gateup(const float* __restrict__ X,
                         const float* __restrict__ WgB,
                         const float* __restrict__ WuB) {
    __shared__ __align__(16) float As[BK][BM + 4];
    __shared__ __align__(16) float Bg[BK][BN];
    __shared__ __align__(16) float Bu[BK][BN];
    __shared__ int   s_tok[BM];
    __shared__ float s_w[BM];

    const int tid = threadIdx.x;
    const int m0  = blockIdx.x * BM;
    const int n0  = blockIdx.y * BN;
    int rows = BM, base = 0;
    const float* Wg = WgB;
    const float* Wu = WuB;
    float* Act = g_shared_act;

    if (GATHER) {
        const int e = blockIdx.z;
        base = g_off[e];
        const int cnt = g_off[e + 1] - base;
        if (m0 >= cnt) return;          // uniform: whole block exits
        rows = min(BM, cnt - m0);
        Wg = WgB + (size_t)e * HH * II;
        Wu = WuB + (size_t)e * HH * II;
        Act = g_routed_act;
        if (tid < BM) {
            if (tid < rows) {
                s_tok[tid] = g_tok[base + m0 + tid];
                s_w[tid]   = g_w[base + m0 + tid];
            } else {
                s_tok[tid] = 0;
                s_w[tid]   = 0.f;
            }
        }
        __syncthreads();
    }

    const int tx = tid & 15, ty = tid >> 4;
    const int a_k4 = tid & 3,  a_row = tid >> 2;   // each thread: one float4 of A
    const int b_c4 = tid & 15, b_kk = tid >> 4;    // each thread: one float4 of B

    bool a_valid = true;
    int  arow;
    if (GATHER) { a_valid = (a_row < rows); arow = s_tok[a_row]; }
    else        { arow = m0 + a_row; }

    const float* Ap = X  + (size_t)arow * HH + a_k4 * 4;
    const float* Gp = Wg + (size_t)b_kk * II + n0 + b_c4 * 4;
    const float* Up = Wu + (size_t)b_kk * II + n0 + b_c4 * 4;

    float ag[4][4], au[4][4];
    #pragma unroll
    for (int i = 0; i < 4; i++)
        #pragma unroll
        for (int j = 0; j < 4; j++) { ag[i][j] = 0.f; au[i][j] = 0.f; }

    for (int k0 = 0; k0 < HH; k0 += BK) {
        float4 av = a_valid ? *(const float4*)(Ap + k0) : make_float4(0.f, 0.f, 0.f, 0.f);
        As[a_k4 * 4 + 0][a_row] = av.x;
        As[a_k4 * 4 + 1][a_row] = av.y;
        As[a_k4 * 4 + 2][a_row] = av.z;
        As[a_k4 * 4 + 3][a_row] = av.w;
        *(float4*)&Bg[b_kk][b_c4 * 4] = *(const float4*)(Gp + (size_t)k0 * II);
        *(float4*)&Bu[b_kk][b_c4 * 4] = *(const float4*)(Up + (size_t)k0 * II);
        __syncthreads();

        #pragma unroll
        for (int kk = 0; kk < BK; kk++) {
            float4 a4 = *(const float4*)&As[kk][ty * 4];
            float4 g4 = *(const float4*)&Bg[kk][tx * 4];
            float4 u4 = *(const float4*)&Bu[kk][tx * 4];
            float aa[4] = {a4.x, a4.y, a4.z, a4.w};
            float gg[4] = {g4.x, g4.y, g4.z, g4.w};
            float uu[4] = {u4.x, u4.y, u4.z, u4.w};
            #pragma unroll
            for (int i = 0; i < 4; i++)
                #pragma unroll
                for (int j = 0; j < 4; j++) {
                    ag[i][j] += aa[i] * gg[j];
                    au[i][j] += aa[i] * uu[j];
                }
        }
        __syncthreads();
    }

    #pragma unroll
    for (int i = 0; i < 4; i++) {
        const int r = ty * 4 + i;
        if (GATHER && r >= rows) break;
        const float scale = GATHER ? s_w[r] : 1.f;
        const int orow = GATHER ? (base + m0 + r) : (m0 + r);
        float v[4];
        #pragma unroll
        for (int j = 0; j < 4; j++) {
            const float g = ag[i][j];
            const float sg = g / (1.f + expf(-g));   // silu
            v[j] = sg * au[i][j] * scale;
        }
        float4 o; o.x = v[0]; o.y = v[1]; o.z = v[2]; o.w = v[3];
        *(float4*)(Act + (size_t)orow * II + n0 + tx * 4) = o;
    }
}

// ---------------- down-projection GEMM --------------------------------------
// shared: Out[m,n] = (act @ Wd)[m,n]   (plain store, covers full output)
// routed: Out[tok,n] += (act @ Wd_e)[m,n]   (atomicAdd scatter)
template <bool GATHER>
__global__ void k_down(const float* __restrict__ WdB, float* __restrict__ Out) {
    __shared__ __align__(16) float As[BK][BM + 4];
    __shared__ __align__(16) float Bs[BK][BN];
    __shared__ int s_tok[BM];

    const int tid = threadIdx.x;
    const int m0  = blockIdx.x * BM;
    const int n0  = blockIdx.y * BN;
    int rows = BM, base = 0;
    const float* Wd = WdB;
    const float* A  = g_shared_act;

    if (GATHER) {
        const int e = blockIdx.z;
        base = g_off[e];
        const int cnt = g_off[e + 1] - base;
        if (m0 >= cnt) return;
        rows = min(BM, cnt - m0);
        Wd = WdB + (size_t)e * II * HH;
        A  = g_routed_act;
        if (tid < BM) s_tok[tid] = (tid < rows) ? g_tok[base + m0 + tid] : 0;
        __syncthreads();
    }

    const int tx = tid & 15, ty = tid >> 4;
    const int a_k4 = tid & 3,  a_row = tid >> 2;
    const int b_c4 = tid & 15, b_kk = tid >> 4;

    const bool a_valid = (!GATHER) || (a_row < rows);
    const int  arow = base + m0 + a_row;   // compact act rows (base=0 for shared)
    const float* Ap = A  + (size_t)arow * II + a_k4 * 4;
    const float* Bp = Wd + (size_t)b_kk * HH + n0 + b_c4 * 4;

    float acc[4][4];
    #pragma unroll
    for (int i = 0; i < 4; i++)
        #pragma unroll
        for (int j = 0; j < 4; j++) acc[i][j] = 0.f;

    for (int k0 = 0; k0 < II; k0 += BK) {
        float4 av = a_valid ? *(const float4*)(Ap + k0) : make_float4(0.f, 0.f, 0.f, 0.f);
        As[a_k4 * 4 + 0][a_row] = av.x;
        As[a_k4 * 4 + 1][a_row] = av.y;
        As[a_k4 * 4 + 2][a_row] = av.z;
        As[a_k4 * 4 + 3][a_row] = av.w;
        *(float4*)&Bs[b_kk][b_c4 * 4] = *(const float4*)(Bp + (size_t)k0 * HH);
        __syncthreads();

        #pragma unroll
        for (int kk = 0; kk < BK; kk++) {
            float4 a4 = *(const float4*)&As[kk][ty * 4];
            float4 b4 = *(const float4*)&Bs[kk][tx * 4];
            float aa[4] = {a4.x, a4.y, a4.z, a4.w};
            float bb[4] = {b4.x, b4.y, b4.z, b4.w};
            #pragma unroll
            for (int i = 0; i < 4; i++)
                #pragma unroll
                for (int j = 0; j < 4; j++) acc[i][j] += aa[i] * bb[j];
        }
        __syncthreads();
    }

    #pragma unroll
    for (int i = 0; i < 4; i++) {
        const int r = ty * 4 + i;
        if (GATHER && r >= rows) break;
        if (GATHER) {
            const int tok = s_tok[r];
            float* op = Out + (size_t)tok * HH + n0 + tx * 4;
            #pragma unroll
            for (int j = 0; j < 4; j++) atomicAdd(op + j, acc[i][j]);
        } else {
            float4 o; o.x = acc[i][0]; o.y = acc[i][1]; o.z = acc[i][2]; o.w = acc[i][3];
            *(float4*)(Out + (size_t)(m0 + r) * HH + n0 + tx * 4) = o;
        }
    }
}

// ---------------- launch -----------------------------------------------------
extern "C" void kernel_launch(void* const* d_in, const int* in_sizes, int n_in,
                              void* d_out, int out_size) {
    (void)in_sizes; (void)n_in; (void)out_size;
    const float* X  = (const float*)d_in[0];  // hidden_states [B,S,H]
    const float* Wr = (const float*)d_in[1];  // router_w      [H,E]
    const float* Sg = (const float*)d_in[2];  // shared_gate_w [H,I]
    const float* Su = (const float*)d_in[3];  // shared_up_w   [H,I]
    const float* Sd = (const float*)d_in[4];  // shared_down_w [I,H]
    const float* Eg = (const float*)d_in[5];  // expert_gate_k [E,H,I]
    const float* Eu = (const float*)d_in[6];  // expert_up_k   [E,H,I]
    const float* Ed = (const float*)d_in[7];  // expert_down_k [E,I,H]
    float* Out = (float*)d_out;               // [B,S,H] fp32

    k_zero<<<1, 64>>>();
    k_router<<<TT, 256>>>(X, Wr);
    k_scan<<<1, 32>>>();
    k_assign<<<TT / 256, 256>>>();

    // shared expert
    k_gateup<false><<<dim3(TT / BM, II / BN, 1), 256>>>(X, Sg, Su);
    k_down<false><<<dim3(TT / BM, HH / BN, 1), 256>>>(Sd, Out);   // writes full Out

    // routed experts (grouped per-expert GEMMs; empty tiles exit immediately)
    k_gateup<true><<<dim3(TT / BM, II / BN, EE), 256>>>(X, Eg, Eu);
    k_down<true><<<dim3(TT / BM, HH / BN, EE), 256>>>(Ed, Out);   // atomicAdd
}

// round 2
// speedup vs baseline: 1.0141x; 1.0141x over previous
#include <cuda_runtime.h>
#include <math.h>

// Problem constants: B=2, S=512 -> TT=1024 tokens, H=1024, I=512, E=64, K=8
#define TT 1024
#define HH 1024
#define II 512
#define EE 64
#define KK 8

#define BM 64
#define BN 64
#define BK 16

// ---------------- device scratch (static globals; no allocation allowed) ----
__device__ int   g_top_idx[TT * KK];
__device__ float g_top_w[TT * KK];
__device__ int   g_count[EE];
__device__ int   g_off[EE + 1];
__device__ int   g_tok[TT * KK];
__device__ float g_w[TT * KK];
__device__ float g_shared_act[TT * II];           // 2 MB
__device__ float g_routed_act[TT * KK * II];      // 16 MB

// ---------------- phase 0: zero per-expert counters ------------------------
__global__ void k_zero() {
    if (threadIdx.x < EE) g_count[threadIdx.x] = 0;
}

// ---------------- phase 1: router (logits -> sigmoid -> top-8) --------------
// one block (256 thr) per token
__global__ void k_router(const float* __restrict__ X, const float* __restrict__ Wr) {
    __shared__ float xs[HH];
    __shared__ float part[4][EE];
    __shared__ float aff[EE];
    const int t = blockIdx.x;
    for (int i = threadIdx.x; i < HH; i += 256) xs[i] = X[(size_t)t * HH + i];
    __syncthreads();

    const int e = threadIdx.x & 63;   // expert
    const int q = threadIdx.x >> 6;   // quarter of H
    float p = 0.f;
    for (int h = q; h < HH; h += 4) p += xs[h] * Wr[h * EE + e];
    part[q][e] = p;
    __syncthreads();

    if (threadIdx.x < EE) {
        float s = part[0][e] + part[1][e] + part[2][e] + part[3][e];
        aff[e] = 1.f / (1.f + expf(-s));
    }
    __syncthreads();

    if (threadIdx.x == 0) {
        float sum = 0.f;
        int   bi[KK];
        float bv[KK];
        #pragma unroll
        for (int k = 0; k < KK; k++) {
            int best = 0; float bvv = -1.f;
            for (int ee = 0; ee < EE; ee++) {
                float v = aff[ee];
                if (v > bvv) { bvv = v; best = ee; }
            }
            bi[k] = best; bv[k] = bvv;
            aff[best] = -1.f;
            sum += bvv;
        }
        const float inv = 1.f / (sum + 1e-9f);
        #pragma unroll
        for (int k = 0; k < KK; k++) {
            g_top_idx[t * KK + k] = bi[k];
            g_top_w[t * KK + k]   = bv[k] * inv;
            atomicAdd(&g_count[bi[k]], 1);
        }
    }
}

// ---------------- phase 2: exclusive scan of counts -------------------------
__global__ void k_scan() {
    if (threadIdx.x == 0) {
        int run = 0;
        for (int e = 0; e < EE; e++) {
            g_off[e] = run;
            run += g_count[e];
            g_count[e] = 0;          // reused as fill cursor in k_assign
        }
        g_off[EE] = run;             // == TT*KK == 8192
    }
}

// ---------------- phase 3: compact per-expert token/weight lists -------------
__global__ void k_assign() {
    const int t = blockIdx.x * blockDim.x + threadIdx.x;
    if (t >= TT) return;
    #pragma unroll
    for (int k = 0; k < KK; k++) {
        const int e    = g_top_idx[t * KK + k];
        const int slot = atomicAdd(&g_count[e], 1);
        const int pos  = g_off[e] + slot;
        g_tok[pos] = t;
        g_w[pos]   = g_top_w[t * KK + k];
    }
}

// ---------------- fused gate+up SwiGLU GEMM ---------------------------------
// C[m, n] = silu(A@Wg)[m,n] * (A@Wu)[m,n] * (row weight if GATHER)
// A: [*, HH] row-major (gathered rows if GATHER). Wg/Wu: [HH, II] row-major.
template <bool GATHER>
__global__ void k_gateup(const float* __restrict__ X,
                         const float* __restrict__ WgB,
                         const float* __restrict__ WuB) {
    __shared__ __align__(16) float As[BK][BM + 4];
    __shared__ __align__(16) float Bg[BK][BN];
    __shared__ __align__(16) float Bu[BK][BN];
    __shared__ int   s_tok[BM];
    __shared__ float s_w[BM];

    const int tid = threadIdx.x;
    const int m0  = blockIdx.x * BM;
    const int n0  = blockIdx.y * BN;
    int rows = BM, base = 0;
    const float* Wg = WgB;
    const float* Wu = WuB;
    float* Act = g_shared_act;

    if (GATHER) {
        const int e = blockIdx.z;
        base = g_off[e];
        const int cnt = g_off[e + 1] - base;
        if (m0 >= cnt) return;          // uniform: whole block exits
        rows = min(BM, cnt - m0);
        Wg = WgB + (size_t)e * HH * II;
        Wu = WuB + (size_t)e * HH * II;
        Act = g_routed_act;
        if (tid < BM) {
            if (tid < rows) {
                s_tok[tid] = g_tok[base + m0 + tid];
                s_w[tid]   = g_w[base + m0 + tid];
            } else {
                s_tok[tid] = 0;
                s_w[tid]   = 0.f;
            }
        }
        __syncthreads();
    }

    const int tx = tid & 15, ty = tid >> 4;
    const int a_k4 = tid & 3,  a_row = tid >> 2;   // each thread: one float4 of A
    const int b_c4 = tid & 15, b_kk = tid >> 4;    // each thread: one float4 of B

    bool a_valid = true;
    int  arow;
    if (GATHER) { a_valid = (a_row < rows); arow = s_tok[a_row]; }
    else        { arow = m0 + a_row; }

    const float* Ap = X  + (size_t)arow * HH + a_k4 * 4;
    const float* Gp = Wg + (size_t)b_kk * II + n0 + b_c4 * 4;
    const float* Up = Wu + (size_t)b_kk * II + n0 + b_c4 * 4;

    float ag[4][4], au[4][4];
    #pragma unroll
    for (int i = 0; i < 4; i++)
        #pragma unroll
        for (int j = 0; j < 4; j++) { ag[i][j] = 0.f; au[i][j] = 0.f; }

    for (int k0 = 0; k0 < HH; k0 += BK) {
        float4 av = a_valid ? *(const float4*)(Ap + k0) : make_float4(0.f, 0.f, 0.f, 0.f);
        As[a_k4 * 4 + 0][a_row] = av.x;
        As[a_k4 * 4 + 1][a_row] = av.y;
        As[a_k4 * 4 + 2][a_row] = av.z;
        As[a_k4 * 4 + 3][a_row] = av.w;
        *(float4*)&Bg[b_kk][b_c4 * 4] = *(const float4*)(Gp + (size_t)k0 * II);
        *(float4*)&Bu[b_kk][b_c4 * 4] = *(const float4*)(Up + (size_t)k0 * II);
        __syncthreads();

        #pragma unroll
        for (int kk = 0; kk < BK; kk++) {
            float4 a4 = *(const float4*)&As[kk][ty * 4];
            float4 g4 = *(const float4*)&Bg[kk][tx * 4];
            float4 u4 = *(const float4*)&Bu[kk][tx * 4];
            float aa[4] = {a4.x, a4.y, a4.z, a4.w};
            float gg[4] = {g4.x, g4.y, g4.z, g4.w};
            float uu[4] = {u4.x, u4.y, u4.z, u4.w};
            #pragma unroll
            for (int i = 0; i < 4; i++)
                #pragma unroll
                for (int j = 0; j < 4; j++) {
                    ag[i][j] += aa[i] * gg[j];
                    au[i][j] += aa[i] * uu[j];
                }
        }
        __syncthreads();
    }

    #pragma unroll
    for (int i = 0; i < 4; i++) {
        const int r = ty * 4 + i;
        if (GATHER && r >= rows) break;
        const float scale = GATHER ? s_w[r] : 1.f;
        const int orow = GATHER ? (base + m0 + r) : (m0 + r);
        float v[4];
        #pragma unroll
        for (int j = 0; j < 4; j++) {
            const float g = ag[i][j];
            const float sg = g / (1.f + expf(-g));   // silu
            v[j] = sg * au[i][j] * scale;
        }
        float4 o; o.x = v[0]; o.y = v[1]; o.z = v[2]; o.w = v[3];
        *(float4*)(Act + (size_t)orow * II + n0 + tx * 4) = o;
    }
}

// ---------------- down-projection GEMM --------------------------------------
// shared: Out[m,n] = (act @ Wd)[m,n]   (plain store, covers full output)
// routed: Out[tok,n] += (act @ Wd_e)[m,n]   (atomicAdd scatter)
template <bool GATHER>
__global__ void k_down(const float* __restrict__ WdB, float* __restrict__ Out) {
    __shared__ __align__(16) float As[BK][BM + 4];
    __shared__ __align__(16) float Bs[BK][BN];
    __shared__ int s_tok[BM];

    const int tid = threadIdx.x;
    const int m0  = blockIdx.x * BM;
    const int n0  = blockIdx.y * BN;
    int rows = BM, base = 0;
    const float* Wd = WdB;
    const float* A  = g_shared_act;

    if (GATHER) {
        const int e = blockIdx.z;
        base = g_off[e];
        const int cnt = g_off[e + 1] - base;
        if (m0 >= cnt) return;
        rows = min(BM, cnt - m0);
        Wd = WdB + (size_t)e * II * HH;
        A  = g_routed_act;
        if (tid < BM) s_tok[tid] = (tid < rows) ? g_tok[base + m0 + tid] : 0;
        __syncthreads();
    }

    const int tx = tid & 15, ty = tid >> 4;
    const int a_k4 = tid & 3,  a_row = tid >> 2;
    const int b_c4 = tid & 15, b_kk = tid >> 4;

    const bool a_valid = (!GATHER) || (a_row < rows);
    const int  arow = base + m0 + a_row;   // compact act rows (base=0 for shared)
    const float* Ap = A  + (size_t)arow * II + a_k4 * 4;
    const float* Bp = Wd + (size_t)b_kk * HH + n0 + b_c4 * 4;

    float acc[4][4];
    #pragma unroll
    for (int i = 0; i < 4; i++)
        #pragma unroll
        for (int j = 0; j < 4; j++) acc[i][j] = 0.f;

    for (int k0 = 0; k0 < II; k0 += BK) {
        float4 av = a_valid ? *(const float4*)(Ap + k0) : make_float4(0.f, 0.f, 0.f, 0.f);
        As[a_k4 * 4 + 0][a_row] = av.x;
        As[a_k4 * 4 + 1][a_row] = av.y;
        As[a_k4 * 4 + 2][a_row] = av.z;
        As[a_k4 * 4 + 3][a_row] = av.w;
        *(float4*)&Bs[b_kk][b_c4 * 4] = *(const float4*)(Bp + (size_t)k0 * HH);
        __syncthreads();

        #pragma unroll
        for (int kk = 0; kk < BK; kk++) {
            float4 a4 = *(const float4*)&As[kk][ty * 4];
            float4 b4 = *(const float4*)&Bs[kk][tx * 4];
            float aa[4] = {a4.x, a4.y, a4.z, a4.w};
            float bb[4] = {b4.x, b4.y, b4.z, b4.w};
            #pragma unroll
            for (int i = 0; i < 4; i++)
                #pragma unroll
                for (int j = 0; j < 4; j++) acc[i][j] += aa[i] * bb[j];
        }
        __syncthreads();
    }

    #pragma unroll
    for (int i = 0; i < 4; i++) {
        const int r = ty * 4 + i;
        if (GATHER && r >= rows) break;
        if (GATHER) {
            const int tok = s_tok[r];
            float* op = Out + (size_t)tok * HH + n0 + tx * 4;
            #pragma unroll
            for (int j = 0; j < 4; j++) atomicAdd(op + j, acc[i][j]);
        } else {
            float4 o; o.x = acc[i][0]; o.y = acc[i][1]; o.z = acc[i][2]; o.w = acc[i][3];
            *(float4*)(Out + (size_t)(m0 + r) * HH + n0 + tx * 4) = o;
        }
    }
}

// ---------------- launch -----------------------------------------------------
extern "C" void kernel_launch(void* const* d_in, const int* in_sizes, int n_in,
                              void* d_out, int out_size) {
    (void)in_sizes; (void)n_in; (void)out_size;
    const float* X  = (const float*)d_in[0];  // hidden_states [B,S,H]
    const float* Wr = (const float*)d_in[1];  // router_w      [H,E]
    const float* Sg = (const float*)d_in[2];  // shared_gate_w [H,I]
    const float* Su = (const float*)d_in[3];  // shared_up_w   [H,I]
    const float* Sd = (const float*)d_in[4];  // shared_down_w [I,H]
    const float* Eg = (const float*)d_in[5];  // expert_gate_k [E,H,I]
    const float* Eu = (const float*)d_in[6];  // expert_up_k   [E,H,I]
    const float* Ed = (const float*)d_in[7];  // expert_down_k [E,I,H]
    float* Out = (float*)d_out;               // [B,S,H] fp32

    k_zero<<<1, 64>>>();
    k_router<<<TT, 256>>>(X, Wr);
    k_scan<<<1, 32>>>();
    k_assign<<<TT / 256, 256>>>();

    // shared expert
    k_gateup<false><<<dim3(TT / BM, II / BN, 1), 256>>>(X, Sg, Su);
    k_down<false><<<dim3(TT / BM, HH / BN, 1), 256>>>(Sd, Out);   // writes full Out

    // routed experts (grouped per-expert GEMMs; empty tiles exit immediately)
    k_gateup<true><<<dim3(TT / BM, II / BN, EE), 256>>>(X, Eg, Eu);
    k_down<true><<<dim3(TT / BM, HH / BN, EE), 256>>>(Ed, Out);   // atomicAdd
}

// round 6
// speedup vs baseline: 1.6981x; 1.6745x over previous
#include <cuda_runtime.h>
#include <cuda_bf16.h>
#include <math.h>
#include <stdint.h>

#define TT 1024
#define HH 1024
#define II 512
#define EE 64
#define KK 8
typedef unsigned short u16;

// ---------------- PTX helpers (base-target sm_103 legal) ---------------------
__device__ __forceinline__ uint32_t smem_u32(const void* p) {
    uint32_t a;
    asm("{ .reg .u64 t; cvta.to.shared.u64 t, %1; cvt.u32.u64 %0, t; }" : "=r"(a) : "l"(p));
    return a;
}
#define CPA16(dst, src) \
    asm volatile("cp.async.cg.shared.global [%0], [%1], 16;" :: "r"(dst), "l"(src))
#define CPA_COMMIT() asm volatile("cp.async.commit_group;" ::: "memory")
#define CPA_WAIT0()  asm volatile("cp.async.wait_group 0;" ::: "memory")
#define CPA_WAIT1()  asm volatile("cp.async.wait_group 1;" ::: "memory")

#define LDSM4(R, addr) \
    asm volatile("ldmatrix.sync.aligned.m8n8.x4.shared.b16 {%0,%1,%2,%3}, [%4];" \
        : "=r"((R)[0]), "=r"((R)[1]), "=r"((R)[2]), "=r"((R)[3]) : "r"(addr))
#define LDSM4T(R, addr) \
    asm volatile("ldmatrix.sync.aligned.m8n8.x4.trans.shared.b16 {%0,%1,%2,%3}, [%4];" \
        : "=r"((R)[0]), "=r"((R)[1]), "=r"((R)[2]), "=r"((R)[3]) : "r"(addr))

#define MMA(D, A, b0, b1) \
    asm volatile("mma.sync.aligned.m16n8k16.row.col.f32.bf16.bf16.f32 " \
        "{%0,%1,%2,%3},{%4,%5,%6,%7},{%8,%9},{%0,%1,%2,%3};" \
        : "+f"((D)[0]), "+f"((D)[1]), "+f"((D)[2]), "+f"((D)[3]) \
        : "r"((A)[0]), "r"((A)[1]), "r"((A)[2]), "r"((A)[3]), "r"(b0), "r"(b1))

// smem swizzles (conflict-free for fills + ldmatrix; audited per-phase)
#define SWA(row, kc) ((uint32_t)(row) * 64u + ((uint32_t)((kc) ^ (((row) >> 1) & 3)) << 4))
#define SWB(kr, cn)  ((uint32_t)(kr) * 128u + ((uint32_t)((cn) ^ ((kr) & 7)) << 4))

// ---------------- bf16 split -------------------------------------------------
__device__ __forceinline__ void split1(float x, u16& h, u16& l) {
    __nv_bfloat16 hb = __float2bfloat16_rn(x);
    __nv_bfloat16 lb = __float2bfloat16_rn(x - __bfloat162float(hb));
    h = *(u16*)&hb; l = *(u16*)&lb;
}

// ---------------- device scratch ---------------------------------------------
__device__ int   g_top_idx[TT * KK];
__device__ float g_top_w[TT * KK];
__device__ int   g_count[EE];
__device__ int   g_off[EE + 1];
__device__ int   g_tok[TT * KK];
__device__ float g_w[TT * KK];
__device__ int   g_pos[TT * KK];
__device__ float g_shared_out[TT * HH];
__device__ float g_down_scratch[TT * KK * HH];
// bf16 hi/lo splits (original layouts, no transpose)
__device__ u16 x_hi[TT * HH], x_lo[TT * HH];
__device__ u16 sact_hi[TT * II], sact_lo[TT * II];
__device__ u16 ract_hi[(TT * KK + 128) * II], ract_lo[(TT * KK + 128) * II];
__device__ u16 c_eg_hi[(size_t)EE * HH * II], c_eg_lo[(size_t)EE * HH * II];
__device__ u16 c_eu_hi[(size_t)EE * HH * II], c_eu_lo[(size_t)EE * HH * II];
__device__ u16 c_ed_hi[(size_t)EE * II * HH], c_ed_lo[(size_t)EE * II * HH];
__device__ u16 c_sg_hi[HH * II], c_sg_lo[HH * II];
__device__ u16 c_su_hi[HH * II], c_su_lo[HH * II];
__device__ u16 c_sd_hi[II * HH], c_sd_lo[II * HH];

// ---------------- elementwise fp32 -> bf16 hi/lo split -----------------------
__global__ void k_split(const float4* __restrict__ s, uint2* __restrict__ hi,
                        uint2* __restrict__ lo, int n4) {
    const int i = blockIdx.x * 256 + threadIdx.x;
    if (i >= n4) return;
    const float4 v = s[i];
    u16 h0,l0,h1,l1,h2,l2,h3,l3;
    split1(v.x,h0,l0); split1(v.y,h1,l1); split1(v.z,h2,l2); split1(v.w,h3,l3);
    hi[i] = make_uint2((uint32_t)h0 | ((uint32_t)h1 << 16), (uint32_t)h2 | ((uint32_t)h3 << 16));
    lo[i] = make_uint2((uint32_t)l0 | ((uint32_t)l1 << 16), (uint32_t)l2 | ((uint32_t)l3 << 16));
}

// ---------------- routing ----------------------------------------------------
__global__ void k_zero() { if (threadIdx.x < EE) g_count[threadIdx.x] = 0; }

__global__ void k_router(const float* __restrict__ X, const float* __restrict__ Wr) {
    __shared__ float xs[HH];
    __shared__ float part[4][EE];
    __shared__ float aff[EE];
    const int t = blockIdx.x;
    for (int i = threadIdx.x; i < HH; i += 256) xs[i] = X[(size_t)t * HH + i];
    __syncthreads();
    const int e = threadIdx.x & 63, q = threadIdx.x >> 6;
    float p = 0.f;
    for (int h = q; h < HH; h += 4) p += xs[h] * Wr[h * EE + e];
    part[q][e] = p;
    __syncthreads();
    if (threadIdx.x < EE) {
        float s = part[0][e] + part[1][e] + part[2][e] + part[3][e];
        aff[e] = 1.f / (1.f + expf(-s));
    }
    __syncthreads();
    if (threadIdx.x == 0) {
        float sum = 0.f; int bi[KK]; float bv[KK];
        #pragma unroll
        for (int k = 0; k < KK; k++) {
            int best = 0; float bvv = -1.f;
            for (int ee = 0; ee < EE; ee++) { float v = aff[ee]; if (v > bvv) { bvv = v; best = ee; } }
            bi[k] = best; bv[k] = bvv; aff[best] = -1.f; sum += bvv;
        }
        const float inv = 1.f / (sum + 1e-9f);
        #pragma unroll
        for (int k = 0; k < KK; k++) {
            g_top_idx[t * KK + k] = bi[k];
            g_top_w[t * KK + k] = bv[k] * inv;
            atomicAdd(&g_count[bi[k]], 1);
        }
    }
}

__global__ void k_scan() {
    if (threadIdx.x == 0) {
        int run = 0;
        for (int e = 0; e < EE; e++) { g_off[e] = run; run += g_count[e]; g_count[e] = 0; }
        g_off[EE] = run;
    }
}

__global__ void k_assign() {
    const int t = blockIdx.x * blockDim.x + threadIdx.x;
    if (t >= TT) return;
    #pragma unroll
    for (int k = 0; k < KK; k++) {
        const int e = g_top_idx[t * KK + k];
        const int pos = g_off[e] + atomicAdd(&g_count[e], 1);
        g_tok[pos] = t;
        g_w[pos] = g_top_w[t * KK + k];
        g_pos[t * KK + k] = pos;
    }
}

// ---------------- gate+up mma.sync GEMM --------------------------------------
// Block 128x64, 8 warps (4m x 2n), K chunks of 32, bf16x3 split, double buffer.
// Buffer (32KB): Ah 8K | Al 8K | Bg_h 4K | Bg_l 4K | Bu_h 4K | Bu_l 4K
#define GU_SMEM (2 * 32768)

template <bool GATHER>
__global__ void __launch_bounds__(256, 1) k_gateup_m() {
    __shared__ int s_tok[128];
    __shared__ float s_w[128];
    extern __shared__ __align__(1024) char dsm[];
    const uint32_t sbase = smem_u32(dsm);
    const int tid = threadIdx.x, wid = tid >> 5, lane = tid & 31;
    const int grp = lane >> 3, lrow = lane & 7;
    const int m0 = blockIdx.x * 128, n0 = blockIdx.y * 64;

    int rows, base;
    const u16 *bgh, *bgl, *buh, *bul;
    u16 *ah_out, *al_out;
    if (GATHER) {
        const int e = blockIdx.z;
        base = g_off[e];
        const int cnt = g_off[e + 1] - base;
        if (m0 >= cnt) return;
        rows = min(128, cnt - m0);
        const size_t wb = (size_t)e * HH * II;
        bgh = c_eg_hi + wb; bgl = c_eg_lo + wb; buh = c_eu_hi + wb; bul = c_eu_lo + wb;
        ah_out = ract_hi; al_out = ract_lo;
    } else {
        base = 0; rows = 128;
        bgh = c_sg_hi; bgl = c_sg_lo; buh = c_su_hi; bul = c_su_lo;
        ah_out = sact_hi; al_out = sact_lo;
    }
    if (tid < 128) {
        if (GATHER) {
            if (tid < rows) { s_tok[tid] = g_tok[base + m0 + tid]; s_w[tid] = g_w[base + m0 + tid]; }
            else            { s_tok[tid] = g_tok[base + m0];       s_w[tid] = 0.f; }
        } else { s_tok[tid] = m0 + tid; s_w[tid] = 1.f; }
    }
    __syncthreads();

    auto fill = [&](int c) {
        const int k0 = c * 32;
        const uint32_t bb = sbase + (uint32_t)(c & 1) * 32768u;
        #pragma unroll
        for (int i = 0; i < 2; i++) {                 // A: 128 rows x 4 kchunks, hi+lo
            const int idx = tid + i * 256, r = idx >> 2, kc = idx & 3;
            const uint32_t d = bb + SWA(r, kc);
            const size_t so = (size_t)s_tok[r] * HH + k0 + kc * 8;
            CPA16(d, x_hi + so);
            CPA16(d + 8192, x_lo + so);
        }
        {                                             // B: 32 k-rows x 8 nchunks, 4 arrays
            const int kr = tid >> 3, cn = tid & 7;
            const uint32_t d = bb + 16384u + SWB(kr, cn);
            const size_t so = (size_t)(k0 + kr) * II + n0 + cn * 8;
            CPA16(d, bgh + so);
            CPA16(d + 4096, bgl + so);
            CPA16(d + 8192, buh + so);
            CPA16(d + 12288, bul + so);
        }
    };

    const int m_w = (wid >> 1) * 32, n_w = (wid & 1) * 32;
    float ag[2][4][4], au[2][4][4];
    #pragma unroll
    for (int a = 0; a < 2; a++)
        #pragma unroll
        for (int b = 0; b < 4; b++)
            #pragma unroll
            for (int r = 0; r < 4; r++) { ag[a][b][r] = 0.f; au[a][b][r] = 0.f; }

    fill(0);
    CPA_COMMIT();
    const int NC = HH / 32;
    for (int c = 0; c < NC; c++) {
        if (c + 1 < NC) { fill(c + 1); CPA_COMMIT(); CPA_WAIT1(); }
        else            { CPA_WAIT0(); }
        __syncthreads();
        const uint32_t bb = sbase + (uint32_t)(c & 1) * 32768u;
        #pragma unroll
        for (int ks = 0; ks < 2; ks++) {
            uint32_t Ah[2][4], Al[2][4];
            #pragma unroll
            for (int mt = 0; mt < 2; mt++) {
                const int arow = m_w + mt * 16 + (grp & 1) * 8 + lrow;
                const int akc = ks * 2 + (grp >> 1);
                const uint32_t aa = bb + SWA(arow, akc);
                LDSM4(Ah[mt], aa);
                LDSM4(Al[mt], aa + 8192);
            }
            const int brow = ks * 16 + (grp & 1) * 8 + lrow;
            #define GU_MAT(ACC, MOFF) {                                                  \
                uint32_t Bh[2][4], Bl[2][4];                                             \
                _Pragma("unroll")                                                        \
                for (int bt = 0; bt < 2; bt++) {                                         \
                    const int bcn = (n_w >> 3) + bt * 2 + (grp >> 1);                    \
                    const uint32_t ba = bb + 16384u + (MOFF) + SWB(brow, bcn);           \
                    LDSM4T(Bh[bt], ba);                                                  \
                    LDSM4T(Bl[bt], ba + 4096);                                           \
                }                                                                        \
                _Pragma("unroll")                                                        \
                for (int mt = 0; mt < 2; mt++)                                           \
                    _Pragma("unroll")                                                    \
                    for (int nt = 0; nt < 4; nt++) {                                     \
                        const uint32_t b0h = Bh[nt >> 1][(nt & 1) * 2];                  \
                        const uint32_t b1h = Bh[nt >> 1][(nt & 1) * 2 + 1];              \
                        const uint32_t b0l = Bl[nt >> 1][(nt & 1) * 2];                  \
                        const uint32_t b1l = Bl[nt >> 1][(nt & 1) * 2 + 1];              \
                        MMA(ACC[mt][nt], Ah[mt], b0h, b1h);                              \
                        MMA(ACC[mt][nt], Ah[mt], b0l, b1l);                              \
                        MMA(ACC[mt][nt], Al[mt], b0h, b1h);                              \
                    }                                                                    \
            }
            GU_MAT(ag, 0u)
            GU_MAT(au, 8192u)
            #undef GU_MAT
        }
        __syncthreads();
    }

    // epilogue: silu(g)*u*w, emit bf16 hi/lo activations (fragment-direct)
    #pragma unroll
    for (int mt = 0; mt < 2; mt++)
        #pragma unroll
        for (int nt = 0; nt < 4; nt++) {
            const int col = n0 + n_w + nt * 8 + (lane & 3) * 2;
            #pragma unroll
            for (int half = 0; half < 2; half++) {
                const int r = m_w + mt * 16 + (lane >> 2) + half * 8;
                if (r < rows) {
                    const float w = s_w[r];
                    const float g0 = ag[mt][nt][half * 2],     u0 = au[mt][nt][half * 2];
                    const float g1 = ag[mt][nt][half * 2 + 1], u1 = au[mt][nt][half * 2 + 1];
                    const float v0 = (g0 / (1.f + __expf(-g0))) * u0 * w;
                    const float v1 = (g1 / (1.f + __expf(-g1))) * u1 * w;
                    u16 h0, l0, h1, l1;
                    split1(v0, h0, l0); split1(v1, h1, l1);
                    const size_t o = (size_t)(base + m0 + r) * II + col;
                    *(uint32_t*)(ah_out + o) = (uint32_t)h0 | ((uint32_t)h1 << 16);
                    *(uint32_t*)(al_out + o) = (uint32_t)l0 | ((uint32_t)l1 << 16);
                }
            }
        }
}

// ---------------- down mma.sync GEMM -----------------------------------------
// Buffer (24KB): Ah 8K | Al 8K | B_h 4K | B_l 4K
#define DN_SMEM (2 * 24576)

template <bool GATHER>
__global__ void __launch_bounds__(256, 1) k_down_m() {
    extern __shared__ __align__(1024) char dsm[];
    const uint32_t sbase = smem_u32(dsm);
    const int tid = threadIdx.x, wid = tid >> 5, lane = tid & 31;
    const int grp = lane >> 3, lrow = lane & 7;
    const int m0 = blockIdx.x * 128, n0 = blockIdx.y * 64;

    int rows, base;
    const u16 *bh_p, *bl_p, *ah_p, *al_p;
    float* Out;
    if (GATHER) {
        const int e = blockIdx.z;
        base = g_off[e];
        const int cnt = g_off[e + 1] - base;
        if (m0 >= cnt) return;
        rows = min(128, cnt - m0);
        const size_t wb = (size_t)e * II * HH;
        bh_p = c_ed_hi + wb; bl_p = c_ed_lo + wb;
        ah_p = ract_hi; al_p = ract_lo;
        Out = g_down_scratch;
    } else {
        base = 0; rows = 128;
        bh_p = c_sd_hi; bl_p = c_sd_lo;
        ah_p = sact_hi; al_p = sact_lo;
        Out = g_shared_out;
    }

    auto fill = [&](int c) {
        const int k0 = c * 32;
        const uint32_t bb = sbase + (uint32_t)(c & 1) * 24576u;
        #pragma unroll
        for (int i = 0; i < 2; i++) {
            const int idx = tid + i * 256, r = idx >> 2, kc = idx & 3;
            const uint32_t d = bb + SWA(r, kc);
            const size_t so = (size_t)(base + m0 + r) * II + k0 + kc * 8;
            CPA16(d, ah_p + so);
            CPA16(d + 8192, al_p + so);
        }
        {
            const int kr = tid >> 3, cn = tid & 7;
            const uint32_t d = bb + 16384u + SWB(kr, cn);
            const size_t so = (size_t)(k0 + kr) * HH + n0 + cn * 8;
            CPA16(d, bh_p + so);
            CPA16(d + 4096, bl_p + so);
        }
    };

    const int m_w = (wid >> 1) * 32, n_w = (wid & 1) * 32;
    float ad[2][4][4];
    #pragma unroll
    for (int a = 0; a < 2; a++)
        #pragma unroll
        for (int b = 0; b < 4; b++)
            #pragma unroll
            for (int r = 0; r < 4; r++) ad[a][b][r] = 0.f;

    fill(0);
    CPA_COMMIT();
    const int NC = II / 32;
    for (int c = 0; c < NC; c++) {
        if (c + 1 < NC) { fill(c + 1); CPA_COMMIT(); CPA_WAIT1(); }
        else            { CPA_WAIT0(); }
        __syncthreads();
        const uint32_t bb = sbase + (uint32_t)(c & 1) * 24576u;
        #pragma unroll
        for (int ks = 0; ks < 2; ks++) {
            uint32_t Ah[2][4], Al[2][4];
            #pragma unroll
            for (int mt = 0; mt < 2; mt++) {
                const int arow = m_w + mt * 16 + (grp & 1) * 8 + lrow;
                const int akc = ks * 2 + (grp >> 1);
                const uint32_t aa = bb + SWA(arow, akc);
                LDSM4(Ah[mt], aa);
                LDSM4(Al[mt], aa + 8192);
            }
            const int brow = ks * 16 + (grp & 1) * 8 + lrow;
            uint32_t Bh[2][4], Bl[2][4];
            #pragma unroll
            for (int bt = 0; bt < 2; bt++) {
                const int bcn = (n_w >> 3) + bt * 2 + (grp >> 1);
                const uint32_t ba = bb + 16384u + SWB(brow, bcn);
                LDSM4T(Bh[bt], ba);
                LDSM4T(Bl[bt], ba + 4096);
            }
            #pragma unroll
            for (int mt = 0; mt < 2; mt++)
                #pragma unroll
                for (int nt = 0; nt < 4; nt++) {
                    const uint32_t b0h = Bh[nt >> 1][(nt & 1) * 2];
                    const uint32_t b1h = Bh[nt >> 1][(nt & 1) * 2 + 1];
                    const uint32_t b0l = Bl[nt >> 1][(nt & 1) * 2];
                    const uint32_t b1l = Bl[nt >> 1][(nt & 1) * 2 + 1];
                    MMA(ad[mt][nt], Ah[mt], b0h, b1h);
                    MMA(ad[mt][nt], Ah[mt], b0l, b1l);
                    MMA(ad[mt][nt], Al[mt], b0h, b1h);
                }
        }
        __syncthreads();
    }

    #pragma unroll
    for (int mt = 0; mt < 2; mt++)
        #pragma unroll
        for (int nt = 0; nt < 4; nt++) {
            const int col = n0 + n_w + nt * 8 + (lane & 3) * 2;
            #pragma unroll
            for (int half = 0; half < 2; half++) {
                const int r = m_w + mt * 16 + (lane >> 2) + half * 8;
                if (r < rows) {
                    float2 st;
                    st.x = ad[mt][nt][half * 2];
                    st.y = ad[mt][nt][half * 2 + 1];
                    *(float2*)(Out + (size_t)(base + m0 + r) * HH + col) = st;
                }
            }
        }
}

// ---------------- combine: Out = shared + gather(routed down) ----------------
__global__ void k_combine(float* __restrict__ Out) {
    const int idx = blockIdx.x * 256 + threadIdx.x;
    const int t = idx >> 10, h = idx & 1023;
    float s = g_shared_out[idx];
    #pragma unroll
    for (int k = 0; k < KK; k++)
        s += g_down_scratch[(size_t)g_pos[t * KK + k] * HH + h];
    Out[idx] = s;
}

// ---------------- launch -----------------------------------------------------
extern "C" void kernel_launch(void* const* d_in, const int* in_sizes, int n_in,
                              void* d_out, int out_size) {
    (void)in_sizes; (void)n_in; (void)out_size;
    const float* X  = (const float*)d_in[0];
    const float* Wr = (const float*)d_in[1];
    const float* Sg = (const float*)d_in[2];
    const float* Su = (const float*)d_in[3];
    const float* Sd = (const float*)d_in[4];
    const float* Eg = (const float*)d_in[5];
    const float* Eu = (const float*)d_in[6];
    const float* Ed = (const float*)d_in[7];
    float* Out = (float*)d_out;

    cudaFuncSetAttribute(k_gateup_m<false>, cudaFuncAttributeMaxDynamicSharedMemorySize, GU_SMEM);
    cudaFuncSetAttribute(k_gateup_m<true>,  cudaFuncAttributeMaxDynamicSharedMemorySize, GU_SMEM);
    cudaFuncSetAttribute(k_down_m<false>,   cudaFuncAttributeMaxDynamicSharedMemorySize, DN_SMEM);
    cudaFuncSetAttribute(k_down_m<true>,    cudaFuncAttributeMaxDynamicSharedMemorySize, DN_SMEM);

    void *xh, *xl, *egh, *egl, *euh, *eul, *edh, *edl, *sgh, *sgl, *suh, *sul, *sdh, *sdl;
    cudaGetSymbolAddress(&xh, x_hi);    cudaGetSymbolAddress(&xl, x_lo);
    cudaGetSymbolAddress(&egh, c_eg_hi); cudaGetSymbolAddress(&egl, c_eg_lo);
    cudaGetSymbolAddress(&euh, c_eu_hi); cudaGetSymbolAddress(&eul, c_eu_lo);
    cudaGetSymbolAddress(&edh, c_ed_hi); cudaGetSymbolAddress(&edl, c_ed_lo);
    cudaGetSymbolAddress(&sgh, c_sg_hi); cudaGetSymbolAddress(&sgl, c_sg_lo);
    cudaGetSymbolAddress(&suh, c_su_hi); cudaGetSymbolAddress(&sul, c_su_lo);
    cudaGetSymbolAddress(&sdh, c_sd_hi); cudaGetSymbolAddress(&sdl, c_sd_lo);

    const int nE = EE * HH * II / 4;       // 8.39M float4
    const int nS = HH * II / 4;            // 131072
    const int nX = TT * HH / 4;            // 262144
    k_split<<<nE / 256, 256>>>((const float4*)Eg, (uint2*)egh, (uint2*)egl, nE);
    k_split<<<nE / 256, 256>>>((const float4*)Eu, (uint2*)euh, (uint2*)eul, nE);
    k_split<<<nE / 256, 256>>>((const float4*)Ed, (uint2*)edh, (uint2*)edl, nE);
    k_split<<<nS / 256, 256>>>((const float4*)Sg, (uint2*)sgh, (uint2*)sgl, nS);
    k_split<<<nS / 256, 256>>>((const float4*)Su, (uint2*)suh, (uint2*)sul, nS);
    k_split<<<nS / 256, 256>>>((const float4*)Sd, (uint2*)sdh, (uint2*)sdl, nS);
    k_split<<<nX / 256, 256>>>((const float4*)X,  (uint2*)xh,  (uint2*)xl,  nX);

    k_zero<<<1, 64>>>();
    k_router<<<TT, 256>>>(X, Wr);
    k_scan<<<1, 32>>>();
    k_assign<<<TT / 256, 256>>>();

    k_gateup_m<false><<<dim3(TT / 128, II / 64, 1), 256, GU_SMEM>>>();
    k_down_m<false><<<dim3(TT / 128, HH / 64, 1), 256, DN_SMEM>>>();

    k_gateup_m<true><<<dim3(TT / 128, II / 64, EE), 256, GU_SMEM>>>();
    k_down_m<true><<<dim3(TT / 128, HH / 64, EE), 256, DN_SMEM>>>();

    k_combine<<<TT * HH / 256, 256>>>(Out);
}

// round 7
// speedup vs baseline: 1.8690x; 1.1007x over previous
#include <cuda_runtime.h>
#include <cuda_bf16.h>
#include <math.h>
#include <stdint.h>

#define TT 1024
#define HH 1024
#define II 512
#define EE 64
#define KK 8
typedef unsigned short u16;

// ---------------- PTX helpers (base-target sm_103 legal) ---------------------
__device__ __forceinline__ uint32_t smem_u32(const void* p) {
    uint32_t a;
    asm("{ .reg .u64 t; cvta.to.shared.u64 t, %1; cvt.u32.u64 %0, t; }" : "=r"(a) : "l"(p));
    return a;
}
#define CPA16(dst, src) \
    asm volatile("cp.async.cg.shared.global [%0], [%1], 16;" :: "r"(dst), "l"(src))
#define CPA_COMMIT() asm volatile("cp.async.commit_group;" ::: "memory")
#define CPA_WAIT0()  asm volatile("cp.async.wait_group 0;" ::: "memory")
#define CPA_WAIT1()  asm volatile("cp.async.wait_group 1;" ::: "memory")

#define LDSM4(R, addr) \
    asm volatile("ldmatrix.sync.aligned.m8n8.x4.shared.b16 {%0,%1,%2,%3}, [%4];" \
        : "=r"((R)[0]), "=r"((R)[1]), "=r"((R)[2]), "=r"((R)[3]) : "r"(addr))
#define LDSM4T(R, addr) \
    asm volatile("ldmatrix.sync.aligned.m8n8.x4.trans.shared.b16 {%0,%1,%2,%3}, [%4];" \
        : "=r"((R)[0]), "=r"((R)[1]), "=r"((R)[2]), "=r"((R)[3]) : "r"(addr))

#define MMA(D, A, b0, b1) \
    asm volatile("mma.sync.aligned.m16n8k16.row.col.f32.bf16.bf16.f32 " \
        "{%0,%1,%2,%3},{%4,%5,%6,%7},{%8,%9},{%0,%1,%2,%3};" \
        : "+f"((D)[0]), "+f"((D)[1]), "+f"((D)[2]), "+f"((D)[3]) \
        : "r"((A)[0]), "r"((A)[1]), "r"((A)[2]), "r"((A)[3]), "r"(b0), "r"(b1))

// smem swizzles (conflict-free for fills + ldmatrix; audited per-phase)
#define SWA(row, kc) ((uint32_t)(row) * 64u + ((uint32_t)((kc) ^ (((row) >> 1) & 3)) << 4))
#define SWB(kr, cn)  ((uint32_t)(kr) * 128u + ((uint32_t)((cn) ^ ((kr) & 7)) << 4))

// ---------------- bf16 split -------------------------------------------------
__device__ __forceinline__ void split1(float x, u16& h, u16& l) {
    __nv_bfloat16 hb = __float2bfloat16_rn(x);
    __nv_bfloat16 lb = __float2bfloat16_rn(x - __bfloat162float(hb));
    h = *(u16*)&hb; l = *(u16*)&lb;
}
__device__ __forceinline__ uint32_t pack2(u16 a, u16 b) {
    return (uint32_t)a | ((uint32_t)b << 16);
}
// split 8 fp32 (two float4) -> 16B hi STS + 16B lo STS
__device__ __forceinline__ void split_sts16(uint32_t dhi, uint32_t dlo, float4 a, float4 b) {
    u16 h[8], l[8];
    split1(a.x, h[0], l[0]); split1(a.y, h[1], l[1]);
    split1(a.z, h[2], l[2]); split1(a.w, h[3], l[3]);
    split1(b.x, h[4], l[4]); split1(b.y, h[5], l[5]);
    split1(b.z, h[6], l[6]); split1(b.w, h[7], l[7]);
    asm volatile("st.shared.v4.b32 [%0], {%1,%2,%3,%4};" :: "r"(dhi),
        "r"(pack2(h[0], h[1])), "r"(pack2(h[2], h[3])),
        "r"(pack2(h[4], h[5])), "r"(pack2(h[6], h[7])));
    asm volatile("st.shared.v4.b32 [%0], {%1,%2,%3,%4};" :: "r"(dlo),
        "r"(pack2(l[0], l[1])), "r"(pack2(l[2], l[3])),
        "r"(pack2(l[4], l[5])), "r"(pack2(l[6], l[7])));
}

// ---------------- device scratch ---------------------------------------------
__device__ int   g_top_idx[TT * KK];
__device__ float g_top_w[TT * KK];
__device__ int   g_count[EE];
__device__ int   g_off[EE + 1];
__device__ int   g_tok[TT * KK];
__device__ float g_w[TT * KK];
__device__ int   g_pos[TT * KK];
__device__ float g_shared_out[TT * HH];
__device__ float g_down_scratch[TT * KK * HH];
// bf16 hi/lo splits for X and activations only (weights convert in-GEMM)
__device__ u16 x_hi[TT * HH], x_lo[TT * HH];
__device__ u16 sact_hi[TT * II], sact_lo[TT * II];
__device__ u16 ract_hi[(TT * KK + 128) * II], ract_lo[(TT * KK + 128) * II];

// ---------------- elementwise fp32 -> bf16 hi/lo split (X only) --------------
__global__ void k_split(const float4* __restrict__ s, uint2* __restrict__ hi,
                        uint2* __restrict__ lo, int n4) {
    const int i = blockIdx.x * 256 + threadIdx.x;
    if (i >= n4) return;
    const float4 v = s[i];
    u16 h0,l0,h1,l1,h2,l2,h3,l3;
    split1(v.x,h0,l0); split1(v.y,h1,l1); split1(v.z,h2,l2); split1(v.w,h3,l3);
    hi[i] = make_uint2(pack2(h0, h1), pack2(h2, h3));
    lo[i] = make_uint2(pack2(l0, l1), pack2(l2, l3));
}

// ---------------- routing ----------------------------------------------------
__global__ void k_zero() { if (threadIdx.x < EE) g_count[threadIdx.x] = 0; }

__global__ void k_router(const float* __restrict__ X, const float* __restrict__ Wr) {
    __shared__ float xs[HH];
    __shared__ float part[4][EE];
    __shared__ float aff[EE];
    const int t = blockIdx.x;
    for (int i = threadIdx.x; i < HH; i += 256) xs[i] = X[(size_t)t * HH + i];
    __syncthreads();
    const int e = threadIdx.x & 63, q = threadIdx.x >> 6;
    float p = 0.f;
    for (int h = q; h < HH; h += 4) p += xs[h] * Wr[h * EE + e];
    part[q][e] = p;
    __syncthreads();
    if (threadIdx.x < EE) {
        float s = part[0][e] + part[1][e] + part[2][e] + part[3][e];
        aff[e] = 1.f / (1.f + expf(-s));
    }
    __syncthreads();
    if (threadIdx.x == 0) {
        float sum = 0.f; int bi[KK]; float bv[KK];
        #pragma unroll
        for (int k = 0; k < KK; k++) {
            int best = 0; float bvv = -1.f;
            for (int ee = 0; ee < EE; ee++) { float v = aff[ee]; if (v > bvv) { bvv = v; best = ee; } }
            bi[k] = best; bv[k] = bvv; aff[best] = -1.f; sum += bvv;
        }
        const float inv = 1.f / (sum + 1e-9f);
        #pragma unroll
        for (int k = 0; k < KK; k++) {
            g_top_idx[t * KK + k] = bi[k];
            g_top_w[t * KK + k] = bv[k] * inv;
            atomicAdd(&g_count[bi[k]], 1);
        }
    }
}

__global__ void k_scan() {
    if (threadIdx.x == 0) {
        int run = 0;
        for (int e = 0; e < EE; e++) { g_off[e] = run; run += g_count[e]; g_count[e] = 0; }
        g_off[EE] = run;
    }
}

__global__ void k_assign() {
    const int t = blockIdx.x * blockDim.x + threadIdx.x;
    if (t >= TT) return;
    #pragma unroll
    for (int k = 0; k < KK; k++) {
        const int e = g_top_idx[t * KK + k];
        const int pos = g_off[e] + atomicAdd(&g_count[e], 1);
        g_tok[pos] = t;
        g_w[pos] = g_top_w[t * KK + k];
        g_pos[t * KK + k] = pos;
    }
}

// ---------------- gate+up mma.sync GEMM --------------------------------------
// Block 128x64, 8 warps (4m x 2n), K chunks of 32, bf16x3 split, double buffer.
// Buffer (32KB): Ah 8K | Al 8K | Bg_h 4K | Bg_l 4K | Bu_h 4K | Bu_l 4K
// Weights arrive as fp32, split to bf16 hi/lo during the smem fill.
#define GU_SMEM (2 * 32768)

template <bool GATHER>
__global__ void __launch_bounds__(256, 1)
k_gateup_m(const float* __restrict__ WgB, const float* __restrict__ WuB) {
    __shared__ int s_tok[128];
    __shared__ float s_w[128];
    extern __shared__ __align__(1024) char dsm[];
    const uint32_t sbase = smem_u32(dsm);
    const int tid = threadIdx.x, wid = tid >> 5, lane = tid & 31;
    const int grp = lane >> 3, lrow = lane & 7;
    const int m0 = blockIdx.x * 128, n0 = blockIdx.y * 64;
    const int kr = tid >> 3, cn = tid & 7;

    int rows, base;
    const float *Wg, *Wu;
    u16 *ah_out, *al_out;
    if (GATHER) {
        const int e = blockIdx.z;
        base = g_off[e];
        const int cnt = g_off[e + 1] - base;
        if (m0 >= cnt) return;
        rows = min(128, cnt - m0);
        const size_t wb = (size_t)e * HH * II;
        Wg = WgB + wb; Wu = WuB + wb;
        ah_out = ract_hi; al_out = ract_lo;
    } else {
        base = 0; rows = 128;
        Wg = WgB; Wu = WuB;
        ah_out = sact_hi; al_out = sact_lo;
    }
    if (tid < 128) {
        if (GATHER) {
            if (tid < rows) { s_tok[tid] = g_tok[base + m0 + tid]; s_w[tid] = g_w[base + m0 + tid]; }
            else            { s_tok[tid] = g_tok[base + m0];       s_w[tid] = 0.f; }
        } else { s_tok[tid] = m0 + tid; s_w[tid] = 1.f; }
    }
    __syncthreads();

    auto fillA = [&](int c) {
        const int k0 = c * 32;
        const uint32_t bb = sbase + (uint32_t)(c & 1) * 32768u;
        #pragma unroll
        for (int i = 0; i < 2; i++) {                 // A: 128 rows x 4 kchunks, hi+lo
            const int idx = tid + i * 256, r = idx >> 2, kc = idx & 3;
            const uint32_t d = bb + SWA(r, kc);
            const size_t so = (size_t)s_tok[r] * HH + k0 + kc * 8;
            CPA16(d, x_hi + so);
            CPA16(d + 8192, x_lo + so);
        }
    };

    float4 rg0, rg1, ru0, ru1;                        // B-chunk register stage
    auto ldgB = [&](int c) {
        const size_t so = (size_t)(c * 32 + kr) * II + n0 + cn * 8;
        const float4* pg = (const float4*)(Wg + so);
        const float4* pu = (const float4*)(Wu + so);
        rg0 = pg[0]; rg1 = pg[1];
        ru0 = pu[0]; ru1 = pu[1];
    };
    auto stsB = [&](int c) {
        const uint32_t d = sbase + (uint32_t)(c & 1) * 32768u + 16384u + SWB(kr, cn);
        split_sts16(d,         d + 4096,  rg0, rg1);
        split_sts16(d + 8192,  d + 12288, ru0, ru1);
    };

    const int m_w = (wid >> 1) * 32, n_w = (wid & 1) * 32;
    float ag[2][4][4], au[2][4][4];
    #pragma unroll
    for (int a = 0; a < 2; a++)
        #pragma unroll
        for (int b = 0; b < 4; b++)
            #pragma unroll
            for (int r = 0; r < 4; r++) { ag[a][b][r] = 0.f; au[a][b][r] = 0.f; }

    ldgB(0);
    fillA(0);
    CPA_COMMIT();
    const int NC = HH / 32;
    for (int c = 0; c < NC; c++) {
        stsB(c);                                       // consume B regs for chunk c
        if (c + 1 < NC) {
            ldgB(c + 1);                               // refill; latency hidden by compute(c)
            fillA(c + 1); CPA_COMMIT(); CPA_WAIT1();
        } else {
            CPA_WAIT0();
        }
        __syncthreads();
        const uint32_t bb = sbase + (uint32_t)(c & 1) * 32768u;
        #pragma unroll
        for (int ks = 0; ks < 2; ks++) {
            uint32_t Ah[2][4], Al[2][4];
            #pragma unroll
            for (int mt = 0; mt < 2; mt++) {
                const int arow = m_w + mt * 16 + (grp & 1) * 8 + lrow;
                const int akc = ks * 2 + (grp >> 1);
                const uint32_t aa = bb + SWA(arow, akc);
                LDSM4(Ah[mt], aa);
                LDSM4(Al[mt], aa + 8192);
            }
            const int brow = ks * 16 + (grp & 1) * 8 + lrow;
            #define GU_MAT(ACC, MOFF) {                                                  \
                uint32_t Bh[2][4], Bl[2][4];                                             \
                _Pragma("unroll")                                                        \
                for (int bt = 0; bt < 2; bt++) {                                         \
                    const int bcn = (n_w >> 3) + bt * 2 + (grp >> 1);                    \
                    const uint32_t ba = bb + 16384u + (MOFF) + SWB(brow, bcn);           \
                    LDSM4T(Bh[bt], ba);                                                  \
                    LDSM4T(Bl[bt], ba + 4096);                                           \
                }                                                                        \
                _Pragma("unroll")                                                        \
                for (int mt = 0; mt < 2; mt++)                                           \
                    _Pragma("unroll")                                                    \
                    for (int nt = 0; nt < 4; nt++) {                                     \
                        const uint32_t b0h = Bh[nt >> 1][(nt & 1) * 2];                  \
                        const uint32_t b1h = Bh[nt >> 1][(nt & 1) * 2 + 1];              \
                        const uint32_t b0l = Bl[nt >> 1][(nt & 1) * 2];                  \
                        const uint32_t b1l = Bl[nt >> 1][(nt & 1) * 2 + 1];              \
                        MMA(ACC[mt][nt], Ah[mt], b0h, b1h);                              \
                        MMA(ACC[mt][nt], Ah[mt], b0l, b1l);                              \
                        MMA(ACC[mt][nt], Al[mt], b0h, b1h);                              \
                    }                                                                    \
            }
            GU_MAT(ag, 0u)
            GU_MAT(au, 8192u)
            #undef GU_MAT
        }
        __syncthreads();
    }

    // epilogue: silu(g)*u*w, emit bf16 hi/lo activations (fragment-direct)
    #pragma unroll
    for (int mt = 0; mt < 2; mt++)
        #pragma unroll
        for (int nt = 0; nt < 4; nt++) {
            const int col = n0 + n_w + nt * 8 + (lane & 3) * 2;
            #pragma unroll
            for (int half = 0; half < 2; half++) {
                const int r = m_w + mt * 16 + (lane >> 2) + half * 8;
                if (r < rows) {
                    const float w = s_w[r];
                    const float g0 = ag[mt][nt][half * 2],     u0 = au[mt][nt][half * 2];
                    const float g1 = ag[mt][nt][half * 2 + 1], u1 = au[mt][nt][half * 2 + 1];
                    const float v0 = (g0 / (1.f + __expf(-g0))) * u0 * w;
                    const float v1 = (g1 / (1.f + __expf(-g1))) * u1 * w;
                    u16 h0, l0, h1, l1;
                    split1(v0, h0, l0); split1(v1, h1, l1);
                    const size_t o = (size_t)(base + m0 + r) * II + col;
                    *(uint32_t*)(ah_out + o) = pack2(h0, h1);
                    *(uint32_t*)(al_out + o) = pack2(l0, l1);
                }
            }
        }
}

// ---------------- down mma.sync GEMM -----------------------------------------
// Buffer (24KB): Ah 8K | Al 8K | B_h 4K | B_l 4K
#define DN_SMEM (2 * 24576)

template <bool GATHER>
__global__ void __launch_bounds__(256, 1)
k_down_m(const float* __restrict__ WdB) {
    extern __shared__ __align__(1024) char dsm[];
    const uint32_t sbase = smem_u32(dsm);
    const int tid = threadIdx.x, wid = tid >> 5, lane = tid & 31;
    const int grp = lane >> 3, lrow = lane & 7;
    const int m0 = blockIdx.x * 128, n0 = blockIdx.y * 64;
    const int kr = tid >> 3, cn = tid & 7;

    int rows, base;
    const float* Wd;
    const u16 *ah_p, *al_p;
    float* Out;
    if (GATHER) {
        const int e = blockIdx.z;
        base = g_off[e];
        const int cnt = g_off[e + 1] - base;
        if (m0 >= cnt) return;
        rows = min(128, cnt - m0);
        Wd = WdB + (size_t)e * II * HH;
        ah_p = ract_hi; al_p = ract_lo;
        Out = g_down_scratch;
    } else {
        base = 0; rows = 128;
        Wd = WdB;
        ah_p = sact_hi; al_p = sact_lo;
        Out = g_shared_out;
    }

    auto fillA = [&](int c) {
        const int k0 = c * 32;
        const uint32_t bb = sbase + (uint32_t)(c & 1) * 24576u;
        #pragma unroll
        for (int i = 0; i < 2; i++) {
            const int idx = tid + i * 256, r = idx >> 2, kc = idx & 3;
            const uint32_t d = bb + SWA(r, kc);
            const size_t so = (size_t)(base + m0 + r) * II + k0 + kc * 8;
            CPA16(d, ah_p + so);
            CPA16(d + 8192, al_p + so);
        }
    };

    float4 rd0, rd1;
    auto ldgB = [&](int c) {
        const size_t so = (size_t)(c * 32 + kr) * HH + n0 + cn * 8;
        const float4* pd = (const float4*)(Wd + so);
        rd0 = pd[0]; rd1 = pd[1];
    };
    auto stsB = [&](int c) {
        const uint32_t d = sbase + (uint32_t)(c & 1) * 24576u + 16384u + SWB(kr, cn);
        split_sts16(d, d + 4096, rd0, rd1);
    };

    const int m_w = (wid >> 1) * 32, n_w = (wid & 1) * 32;
    float ad[2][4][4];
    #pragma unroll
    for (int a = 0; a < 2; a++)
        #pragma unroll
        for (int b = 0; b < 4; b++)
            #pragma unroll
            for (int r = 0; r < 4; r++) ad[a][b][r] = 0.f;

    ldgB(0);
    fillA(0);
    CPA_COMMIT();
    const int NC = II / 32;
    for (int c = 0; c < NC; c++) {
        stsB(c);
        if (c + 1 < NC) {
            ldgB(c + 1);
            fillA(c + 1); CPA_COMMIT(); CPA_WAIT1();
        } else {
            CPA_WAIT0();
        }
        __syncthreads();
        const uint32_t bb = sbase + (uint32_t)(c & 1) * 24576u;
        #pragma unroll
        for (int ks = 0; ks < 2; ks++) {
            uint32_t Ah[2][4], Al[2][4];
            #pragma unroll
            for (int mt = 0; mt < 2; mt++) {
                const int arow = m_w + mt * 16 + (grp & 1) * 8 + lrow;
                const int akc = ks * 2 + (grp >> 1);
                const uint32_t aa = bb + SWA(arow, akc);
                LDSM4(Ah[mt], aa);
                LDSM4(Al[mt], aa + 8192);
            }
            const int brow = ks * 16 + (grp & 1) * 8 + lrow;
            uint32_t Bh[2][4], Bl[2][4];
            #pragma unroll
            for (int bt = 0; bt < 2; bt++) {
                const int bcn = (n_w >> 3) + bt * 2 + (grp >> 1);
                const uint32_t ba = bb + 16384u + SWB(brow, bcn);
                LDSM4T(Bh[bt], ba);
                LDSM4T(Bl[bt], ba + 4096);
            }
            #pragma unroll
            for (int mt = 0; mt < 2; mt++)
                #pragma unroll
                for (int nt = 0; nt < 4; nt++) {
                    const uint32_t b0h = Bh[nt >> 1][(nt & 1) * 2];
                    const uint32_t b1h = Bh[nt >> 1][(nt & 1) * 2 + 1];
                    const uint32_t b0l = Bl[nt >> 1][(nt & 1) * 2];
                    const uint32_t b1l = Bl[nt >> 1][(nt & 1) * 2 + 1];
                    MMA(ad[mt][nt], Ah[mt], b0h, b1h);
                    MMA(ad[mt][nt], Ah[mt], b0l, b1l);
                    MMA(ad[mt][nt], Al[mt], b0h, b1h);
                }
        }
        __syncthreads();
    }

    #pragma unroll
    for (int mt = 0; mt < 2; mt++)
        #pragma unroll
        for (int nt = 0; nt < 4; nt++) {
            const int col = n0 + n_w + nt * 8 + (lane & 3) * 2;
            #pragma unroll
            for (int half = 0; half < 2; half++) {
                const int r = m_w + mt * 16 + (lane >> 2) + half * 8;
                if (r < rows) {
                    float2 st;
                    st.x = ad[mt][nt][half * 2];
                    st.y = ad[mt][nt][half * 2 + 1];
                    *(float2*)(Out + (size_t)(base + m0 + r) * HH + col) = st;
                }
            }
        }
}

// ---------------- combine: Out = shared + gather(routed down) ----------------
__global__ void k_combine(float* __restrict__ Out) {
    const int idx = blockIdx.x * 256 + threadIdx.x;
    const int t = idx >> 10, h = idx & 1023;
    float s = g_shared_out[idx];
    #pragma unroll
    for (int k = 0; k < KK; k++)
        s += g_down_scratch[(size_t)g_pos[t * KK + k] * HH + h];
    Out[idx] = s;
}

// ---------------- launch -----------------------------------------------------
extern "C" void kernel_launch(void* const* d_in, const int* in_sizes, int n_in,
                              void* d_out, int out_size) {
    (void)in_sizes; (void)n_in; (void)out_size;
    const float* X  = (const float*)d_in[0];
    const float* Wr = (const float*)d_in[1];
    const float* Sg = (const float*)d_in[2];
    const float* Su = (const float*)d_in[3];
    const float* Sd = (const float*)d_in[4];
    const float* Eg = (const float*)d_in[5];
    const float* Eu = (const float*)d_in[6];
    const float* Ed = (const float*)d_in[7];
    float* Out = (float*)d_out;

    cudaFuncSetAttribute(k_gateup_m<false>, cudaFuncAttributeMaxDynamicSharedMemorySize, GU_SMEM);
    cudaFuncSetAttribute(k_gateup_m<true>,  cudaFuncAttributeMaxDynamicSharedMemorySize, GU_SMEM);
    cudaFuncSetAttribute(k_down_m<false>,   cudaFuncAttributeMaxDynamicSharedMemorySize, DN_SMEM);
    cudaFuncSetAttribute(k_down_m<true>,    cudaFuncAttributeMaxDynamicSharedMemorySize, DN_SMEM);

    void *xh, *xl;
    cudaGetSymbolAddress(&xh, x_hi);
    cudaGetSymbolAddress(&xl, x_lo);

    const int nX = TT * HH / 4;            // 262144 float4
    k_split<<<nX / 256, 256>>>((const float4*)X, (uint2*)xh, (uint2*)xl, nX);

    k_zero<<<1, 64>>>();
    k_router<<<TT, 256>>>(X, Wr);
    k_scan<<<1, 32>>>();
    k_assign<<<TT / 256, 256>>>();

    k_gateup_m<false><<<dim3(TT / 128, II / 64, 1), 256, GU_SMEM>>>(Sg, Su);
    k_down_m<false><<<dim3(TT / 128, HH / 64, 1), 256, DN_SMEM>>>(Sd);

    k_gateup_m<true><<<dim3(TT / 128, II / 64, EE), 256, GU_SMEM>>>(Eg, Eu);
    k_down_m<true><<<dim3(TT / 128, HH / 64, EE), 256, DN_SMEM>>>(Ed);

    k_combine<<<TT * HH / 256, 256>>>(Out);
}

// round 15
// speedup vs baseline: 2.1713x; 1.1617x over previous
#include <cuda_runtime.h>
#include <cuda_bf16.h>
#include <math.h>
#include <stdint.h>

#define TT 1024
#define HH 1024
#define II 512
#define EE 64
#define KK 8
typedef unsigned short u16;

// ---------------- PTX helpers (base-target sm_103 legal) ---------------------
__device__ __forceinline__ uint32_t smem_u32(const void* p) {
    uint32_t a;
    asm("{ .reg .u64 t; cvta.to.shared.u64 t, %1; cvt.u32.u64 %0, t; }" : "=r"(a) : "l"(p));
    return a;
}
#define CPA16(dst, src) \
    asm volatile("cp.async.cg.shared.global [%0], [%1], 16;" :: "r"(dst), "l"(src))
#define CPA_COMMIT() asm volatile("cp.async.commit_group;" ::: "memory")
#define CPA_WAIT0()  asm volatile("cp.async.wait_group 0;" ::: "memory")
#define CPA_WAIT1()  asm volatile("cp.async.wait_group 1;" ::: "memory")

#define LDSM4(R, addr) \
    asm volatile("ldmatrix.sync.aligned.m8n8.x4.shared.b16 {%0,%1,%2,%3}, [%4];" \
        : "=r"((R)[0]), "=r"((R)[1]), "=r"((R)[2]), "=r"((R)[3]) : "r"(addr))
#define LDSM4T(R, addr) \
    asm volatile("ldmatrix.sync.aligned.m8n8.x4.trans.shared.b16 {%0,%1,%2,%3}, [%4];" \
        : "=r"((R)[0]), "=r"((R)[1]), "=r"((R)[2]), "=r"((R)[3]) : "r"(addr))

#define MMA(D, A, b0, b1) \
    asm volatile("mma.sync.aligned.m16n8k16.row.col.f32.bf16.bf16.f32 " \
        "{%0,%1,%2,%3},{%4,%5,%6,%7},{%8,%9},{%0,%1,%2,%3};" \
        : "+f"((D)[0]), "+f"((D)[1]), "+f"((D)[2]), "+f"((D)[3]) \
        : "r"((A)[0]), "r"((A)[1]), "r"((A)[2]), "r"((A)[3]), "r"(b0), "r"(b1))

// smem swizzles (conflict-free for fills + ldmatrix; audited per-phase)
#define SWA(row, kc) ((uint32_t)(row) * 64u + ((uint32_t)((kc) ^ (((row) >> 1) & 3)) << 4))
#define SWB(kr, cn)  ((uint32_t)(kr) * 128u + ((uint32_t)((cn) ^ ((kr) & 7)) << 4))

// ---------------- bf16 split -------------------------------------------------
__device__ __forceinline__ void split1(float x, u16& h, u16& l) {
    __nv_bfloat16 hb = __float2bfloat16_rn(x);
    __nv_bfloat16 lb = __float2bfloat16_rn(x - __bfloat162float(hb));
    h = *(u16*)&hb; l = *(u16*)&lb;
}
__device__ __forceinline__ uint32_t pack2(u16 a, u16 b) {
    return (uint32_t)a | ((uint32_t)b << 16);
}
// split 8 fp32 (two float4) -> 16B hi STS + 16B lo STS
__device__ __forceinline__ void split_sts16(uint32_t dhi, uint32_t dlo, float4 a, float4 b) {
    u16 h[8], l[8];
    split1(a.x, h[0], l[0]); split1(a.y, h[1], l[1]);
    split1(a.z, h[2], l[2]); split1(a.w, h[3], l[3]);
    split1(b.x, h[4], l[4]); split1(b.y, h[5], l[5]);
    split1(b.z, h[6], l[6]); split1(b.w, h[7], l[7]);
    asm volatile("st.shared.v4.b32 [%0], {%1,%2,%3,%4};" :: "r"(dhi),
        "r"(pack2(h[0], h[1])), "r"(pack2(h[2], h[3])),
        "r"(pack2(h[4], h[5])), "r"(pack2(h[6], h[7])));
    asm volatile("st.shared.v4.b32 [%0], {%1,%2,%3,%4};" :: "r"(dlo),
        "r"(pack2(l[0], l[1])), "r"(pack2(l[2], l[3])),
        "r"(pack2(l[4], l[5])), "r"(pack2(l[6], l[7])));
}

// ---------------- device scratch ---------------------------------------------
__device__ int   g_top_idx[TT * KK];
__device__ float g_top_w[TT * KK];
__device__ int   g_count[EE];
__device__ int   g_off[EE + 1];
__device__ int   g_tok[TT * KK];
__device__ float g_w[TT * KK];
__device__ int   g_pos[TT * KK];
__device__ float g_shared_out[TT * HH];
__device__ float g_down_scratch[TT * KK * HH];
__device__ u16 x_hi[TT * HH], x_lo[TT * HH];
__device__ u16 sact_hi[TT * II], sact_lo[TT * II];
__device__ u16 ract_hi[(TT * KK + 128) * II], ract_lo[(TT * KK + 128) * II];

// ---------------- routing (X hi/lo split fused in) ----------------------------
__global__ void k_zero() { if (threadIdx.x < EE) g_count[threadIdx.x] = 0; }

__global__ void k_router(const float* __restrict__ X, const float* __restrict__ Wr) {
    __shared__ float xs[HH];
    __shared__ float part[4][EE];
    __shared__ float aff[EE];
    const int t = blockIdx.x;
    for (int i = threadIdx.x; i < HH; i += 256) xs[i] = X[(size_t)t * HH + i];
    __syncthreads();

    // fused X split: each thread packs 4 consecutive elements -> 8B hi + 8B lo
    {
        const int i = threadIdx.x * 4;
        u16 h0,l0,h1,l1,h2,l2,h3,l3;
        split1(xs[i],     h0, l0); split1(xs[i + 1], h1, l1);
        split1(xs[i + 2], h2, l2); split1(xs[i + 3], h3, l3);
        *(uint2*)(x_hi + (size_t)t * HH + i) = make_uint2(pack2(h0, h1), pack2(h2, h3));
        *(uint2*)(x_lo + (size_t)t * HH + i) = make_uint2(pack2(l0, l1), pack2(l2, l3));
    }

    const int e = threadIdx.x & 63, q = threadIdx.x >> 6;
    float p = 0.f;
    for (int h = q; h < HH; h += 4) p += xs[h] * Wr[h * EE + e];
    part[q][e] = p;
    __syncthreads();
    if (threadIdx.x < EE) {
        float s = part[0][e] + part[1][e] + part[2][e] + part[3][e];
        aff[e] = 1.f / (1.f + expf(-s));
    }
    __syncthreads();
    if (threadIdx.x == 0) {
        float sum = 0.f; int bi[KK]; float bv[KK];
        #pragma unroll
        for (int k = 0; k < KK; k++) {
            int best = 0; float bvv = -1.f;
            for (int ee = 0; ee < EE; ee++) { float v = aff[ee]; if (v > bvv) { bvv = v; best = ee; } }
            bi[k] = best; bv[k] = bvv; aff[best] = -1.f; sum += bvv;
        }
        const float inv = 1.f / (sum + 1e-9f);
        #pragma unroll
        for (int k = 0; k < KK; k++) {
            g_top_idx[t * KK + k] = bi[k];
            g_top_w[t * KK + k] = bv[k] * inv;
            atomicAdd(&g_count[bi[k]], 1);
        }
    }
}

// parallel exclusive scan over 64 expert counts (Hillis-Steele)
__global__ void k_scan() {
    __shared__ int sc[EE];
    const int e = threadIdx.x;          // 64 threads
    sc[e] = g_count[e];
    __syncthreads();
    #pragma unroll
    for (int off = 1; off < EE; off <<= 1) {
        const int t = (e >= off) ? sc[e - off] : 0;
        __syncthreads();
        sc[e] += t;
        __syncthreads();
    }
    g_off[e + 1] = sc[e];
    if (e == 0) g_off[0] = 0;
    g_count[e] = 0;                      // reused as fill cursor
}

__global__ void k_assign() {
    const int t = blockIdx.x * blockDim.x + threadIdx.x;
    if (t >= TT) return;
    #pragma unroll
    for (int k = 0; k < KK; k++) {
        const int e = g_top_idx[t * KK + k];
        const int pos = g_off[e] + atomicAdd(&g_count[e], 1);
        g_tok[pos] = t;
        g_w[pos] = g_top_w[t * KK + k];
        g_pos[t * KK + k] = pos;
    }
}

// ---------------- gate+up mma.sync GEMM (routed + shared, z = EE+1) -----------
// Block 128x64, 8 warps (4m x 2n), K chunks of 32, bf16x3 split, double buffer.
// Buffer (32KB): Ah 8K | Al 8K | Bg_h 4K | Bg_l 4K | Bu_h 4K | Bu_l 4K
#define GU_SMEM (2 * 32768)

__global__ void __launch_bounds__(256, 1)
k_gateup_m(const float* __restrict__ Sg, const float* __restrict__ Su,
           const float* __restrict__ EgB, const float* __restrict__ EuB) {
    __shared__ int s_tok[128];
    __shared__ float s_w[128];
    extern __shared__ __align__(1024) char dsm[];
    const uint32_t sbase = smem_u32(dsm);
    const int tid = threadIdx.x, wid = tid >> 5, lane = tid & 31;
    const int grp = lane >> 3, lrow = lane & 7;
    const int m0 = blockIdx.x * 128, n0 = blockIdx.y * 64;
    const int kr = tid >> 3, cn = tid & 7;
    const int e = blockIdx.z;

    int rows, base;
    const float *Wg, *Wu;
    u16 *ah_out, *al_out;
    if (e < EE) {
        base = g_off[e];
        const int cnt = g_off[e + 1] - base;
        if (m0 >= cnt) return;
        rows = min(128, cnt - m0);
        const size_t wb = (size_t)e * HH * II;
        Wg = EgB + wb; Wu = EuB + wb;
        ah_out = ract_hi; al_out = ract_lo;
    } else {
        base = 0; rows = 128;
        Wg = Sg; Wu = Su;
        ah_out = sact_hi; al_out = sact_lo;
    }
    if (tid < 128) {
        if (e < EE) {
            if (tid < rows) { s_tok[tid] = g_tok[base + m0 + tid]; s_w[tid] = g_w[base + m0 + tid]; }
            else            { s_tok[tid] = g_tok[base + m0];       s_w[tid] = 0.f; }
        } else { s_tok[tid] = m0 + tid; s_w[tid] = 1.f; }
    }
    __syncthreads();

    auto fillA = [&](int c) {
        const int k0 = c * 32;
        const uint32_t bb = sbase + (uint32_t)(c & 1) * 32768u;
        #pragma unroll
        for (int i = 0; i < 2; i++) {
            const int idx = tid + i * 256, r = idx >> 2, kc = idx & 3;
            const uint32_t d = bb + SWA(r, kc);
            const size_t so = (size_t)s_tok[r] * HH + k0 + kc * 8;
            CPA16(d, x_hi + so);
            CPA16(d + 8192, x_lo + so);
        }
    };

    float4 rg0, rg1, ru0, ru1;
    auto ldgB = [&](int c) {
        const size_t so = (size_t)(c * 32 + kr) * II + n0 + cn * 8;
        const float4* pg = (const float4*)(Wg + so);
        const float4* pu = (const float4*)(Wu + so);
        rg0 = pg[0]; rg1 = pg[1];
        ru0 = pu[0]; ru1 = pu[1];
    };
    auto stsB = [&](int c) {
        const uint32_t d = sbase + (uint32_t)(c & 1) * 32768u + 16384u + SWB(kr, cn);
        split_sts16(d,         d + 4096,  rg0, rg1);
        split_sts16(d + 8192,  d + 12288, ru0, ru1);
    };

    const int m_w = (wid >> 1) * 32, n_w = (wid & 1) * 32;
    const bool act_w = (m_w < rows);     // partial-tile warp skip
    float ag[2][4][4], au[2][4][4];
    #pragma unroll
    for (int a = 0; a < 2; a++)
        #pragma unroll
        for (int b = 0; b < 4; b++)
            #pragma unroll
            for (int r = 0; r < 4; r++) { ag[a][b][r] = 0.f; au[a][b][r] = 0.f; }

    ldgB(0);
    fillA(0);
    CPA_COMMIT();
    const int NC = HH / 32;
    for (int c = 0; c < NC; c++) {
        stsB(c);
        if (c + 1 < NC) {
            ldgB(c + 1);
            fillA(c + 1); CPA_COMMIT(); CPA_WAIT1();
        } else {
            CPA_WAIT0();
        }
        __syncthreads();
        if (act_w) {
            const uint32_t bb = sbase + (uint32_t)(c & 1) * 32768u;
            #pragma unroll
            for (int ks = 0; ks < 2; ks++) {
                uint32_t Ah[2][4], Al[2][4];
                #pragma unroll
                for (int mt = 0; mt < 2; mt++) {
                    const int arow = m_w + mt * 16 + (grp & 1) * 8 + lrow;
                    const int akc = ks * 2 + (grp >> 1);
                    const uint32_t aa = bb + SWA(arow, akc);
                    LDSM4(Ah[mt], aa);
                    LDSM4(Al[mt], aa + 8192);
                }
                const int brow = ks * 16 + (grp & 1) * 8 + lrow;
                #define GU_MAT(ACC, MOFF) {                                              \
                    uint32_t Bh[2][4], Bl[2][4];                                         \
                    _Pragma("unroll")                                                    \
                    for (int bt = 0; bt < 2; bt++) {                                     \
                        const int bcn = (n_w >> 3) + bt * 2 + (grp >> 1);                \
                        const uint32_t ba = bb + 16384u + (MOFF) + SWB(brow, bcn);       \
                        LDSM4T(Bh[bt], ba);                                              \
                        LDSM4T(Bl[bt], ba + 4096);                                       \
                    }                                                                    \
                    _Pragma("unroll")                                                    \
                    for (int mt = 0; mt < 2; mt++)                                       \
                        _Pragma("unroll")                                                \
                        for (int nt = 0; nt < 4; nt++) {                                 \
                            const uint32_t b0h = Bh[nt >> 1][(nt & 1) * 2];              \
                            const uint32_t b1h = Bh[nt >> 1][(nt & 1) * 2 + 1];          \
                            const uint32_t b0l = Bl[nt >> 1][(nt & 1) * 2];              \
                            const uint32_t b1l = Bl[nt >> 1][(nt & 1) * 2 + 1];          \
                            MMA(ACC[mt][nt], Ah[mt], b0h, b1h);                          \
                            MMA(ACC[mt][nt], Ah[mt], b0l, b1l);                          \
                            MMA(ACC[mt][nt], Al[mt], b0h, b1h);                          \
                        }                                                                \
                }
                GU_MAT(ag, 0u)
                GU_MAT(au, 8192u)
                #undef GU_MAT
            }
        }
        __syncthreads();
    }

    if (act_w) {
        #pragma unroll
        for (int mt = 0; mt < 2; mt++)
            #pragma unroll
            for (int nt = 0; nt < 4; nt++) {
                const int col = n0 + n_w + nt * 8 + (lane & 3) * 2;
                #pragma unroll
                for (int half = 0; half < 2; half++) {
                    const int r = m_w + mt * 16 + (lane >> 2) + half * 8;
                    if (r < rows) {
                        const float w = s_w[r];
                        const float g0 = ag[mt][nt][half * 2],     u0 = au[mt][nt][half * 2];
                        const float g1 = ag[mt][nt][half * 2 + 1], u1 = au[mt][nt][half * 2 + 1];
                        const float v0 = (g0 / (1.f + __expf(-g0))) * u0 * w;
                        const float v1 = (g1 / (1.f + __expf(-g1))) * u1 * w;
                        u16 h0, l0, h1, l1;
                        split1(v0, h0, l0); split1(v1, h1, l1);
                        const size_t o = (size_t)(base + m0 + r) * II + col;
                        *(uint32_t*)(ah_out + o) = pack2(h0, h1);
                        *(uint32_t*)(al_out + o) = pack2(l0, l1);
                    }
                }
            }
    }
}

// ---------------- down mma.sync GEMM (routed + shared, z = EE+1) ---------------
// Buffer (24KB): Ah 8K | Al 8K | B_h 4K | B_l 4K
#define DN_SMEM (2 * 24576)

__global__ void __launch_bounds__(256, 2)
k_down_m(const float* __restrict__ Sd, const float* __restrict__ EdB) {
    extern __shared__ __align__(1024) char dsm[];
    const uint32_t sbase = smem_u32(dsm);
    const int tid = threadIdx.x, wid = tid >> 5, lane = tid & 31;
    const int grp = lane >> 3, lrow = lane & 7;
    const int m0 = blockIdx.x * 128, n0 = blockIdx.y * 64;
    const int kr = tid >> 3, cn = tid & 7;
    const int e = blockIdx.z;

    int rows, base;
    const float* Wd;
    const u16 *ah_p, *al_p;
    float* Out;
    if (e < EE) {
        base = g_off[e];
        const int cnt = g_off[e + 1] - base;
        if (m0 >= cnt) return;
        rows = min(128, cnt - m0);
        Wd = EdB + (size_t)e * II * HH;
        ah_p = ract_hi; al_p = ract_lo;
        Out = g_down_scratch;
    } else {
        base = 0; rows = 128;
        Wd = Sd;
        ah_p = sact_hi; al_p = sact_lo;
        Out = g_shared_out;
    }

    auto fillA = [&](int c) {
        const int k0 = c * 32;
        const uint32_t bb = sbase + (uint32_t)(c & 1) * 24576u;
        #pragma unroll
        for (int i = 0; i < 2; i++) {
            const int idx = tid + i * 256, r = idx >> 2, kc = idx & 3;
            const uint32_t d = bb + SWA(r, kc);
            const size_t so = (size_t)(base + m0 + r) * II + k0 + kc * 8;
            CPA16(d, ah_p + so);
            CPA16(d + 8192, al_p + so);
        }
    };

    float4 rd0, rd1;
    auto ldgB = [&](int c) {
        const size_t so = (size_t)(c * 32 + kr) * HH + n0 + cn * 8;
        const float4* pd = (const float4*)(Wd + so);
        rd0 = pd[0]; rd1 = pd[1];
    };
    auto stsB = [&](int c) {
        const uint32_t d = sbase + (uint32_t)(c & 1) * 24576u + 16384u + SWB(kr, cn);
        split_sts16(d, d + 4096, rd0, rd1);
    };

    const int m_w = (wid >> 1) * 32, n_w = (wid & 1) * 32;
    const bool act_w = (m_w < rows);
    float ad[2][4][4];
    #pragma unroll
    for (int a = 0; a < 2; a++)
        #pragma unroll
        for (int b = 0; b < 4; b++)
            #pragma unroll
            for (int r = 0; r < 4; r++) ad[a][b][r] = 0.f;

    ldgB(0);
    fillA(0);
    CPA_COMMIT();
    const int NC = II / 32;
    for (int c = 0; c < NC; c++) {
        stsB(c);
        if (c + 1 < NC) {
            ldgB(c + 1);
            fillA(c + 1); CPA_COMMIT(); CPA_WAIT1();
        } else {
            CPA_WAIT0();
        }
        __syncthreads();
        if (act_w) {
            const uint32_t bb = sbase + (uint32_t)(c & 1) * 24576u;
            #pragma unroll
            for (int ks = 0; ks < 2; ks++) {
                uint32_t Ah[2][4], Al[2][4];
                #pragma unroll
                for (int mt = 0; mt < 2; mt++) {
                    const int arow = m_w + mt * 16 + (grp & 1) * 8 + lrow;
                    const int akc = ks * 2 + (grp >> 1);
                    const uint32_t aa = bb + SWA(arow, akc);
                    LDSM4(Ah[mt], aa);
                    LDSM4(Al[mt], aa + 8192);
                }
                const int brow = ks * 16 + (grp & 1) * 8 + lrow;
                uint32_t Bh[2][4], Bl[2][4];
                #pragma unroll
                for (int bt = 0; bt < 2; bt++) {
                    const int bcn = (n_w >> 3) + bt * 2 + (grp >> 1);
                    const uint32_t ba = bb + 16384u + SWB(brow, bcn);
                    LDSM4T(Bh[bt], ba);
                    LDSM4T(Bl[bt], ba + 4096);
                }
                #pragma unroll
                for (int mt = 0; mt < 2; mt++)
                    #pragma unroll
                    for (int nt = 0; nt < 4; nt++) {
                        const uint32_t b0h = Bh[nt >> 1][(nt & 1) * 2];
                        const uint32_t b1h = Bh[nt >> 1][(nt & 1) * 2 + 1];
                        const uint32_t b0l = Bl[nt >> 1][(nt & 1) * 2];
                        const uint32_t b1l = Bl[nt >> 1][(nt & 1) * 2 + 1];
                        MMA(ad[mt][nt], Ah[mt], b0h, b1h);
                        MMA(ad[mt][nt], Ah[mt], b0l, b1l);
                        MMA(ad[mt][nt], Al[mt], b0h, b1h);
                    }
            }
        }
        __syncthreads();
    }

    if (act_w) {
        #pragma unroll
        for (int mt = 0; mt < 2; mt++)
            #pragma unroll
            for (int nt = 0; nt < 4; nt++) {
                const int col = n0 + n_w + nt * 8 + (lane & 3) * 2;
                #pragma unroll
                for (int half = 0; half < 2; half++) {
                    const int r = m_w + mt * 16 + (lane >> 2) + half * 8;
                    if (r < rows) {
                        float2 st;
                        st.x = ad[mt][nt][half * 2];
                        st.y = ad[mt][nt][half * 2 + 1];
                        *(float2*)(Out + (size_t)(base + m0 + r) * HH + col) = st;
                    }
                }
            }
    }
}

// ---------------- combine: Out = shared + gather(routed down), float4 ---------
__global__ void k_combine(float* __restrict__ Out) {
    const int i4 = blockIdx.x * 256 + threadIdx.x;    // over TT*HH/4
    const int t = i4 >> 8, h4 = (i4 & 255) * 4;       // 256 float4 per token row
    const size_t eb = (size_t)t * HH + h4;
    float4 s = *(const float4*)(g_shared_out + eb);
    #pragma unroll
    for (int k = 0; k < KK; k++) {
        const float4 v = *(const float4*)(g_down_scratch + (size_t)g_pos[t * KK + k] * HH + h4);
        s.x += v.x; s.y += v.y; s.z += v.z; s.w += v.w;
    }
    *(float4*)(Out + eb) = s;
}

// ---------------- launch -----------------------------------------------------
extern "C" void kernel_launch(void* const* d_in, const int* in_sizes, int n_in,
                              void* d_out, int out_size) {
    (void)in_sizes; (void)n_in; (void)out_size;
    const float* X  = (const float*)d_in[0];
    const float* Wr = (const float*)d_in[1];
    const float* Sg = (const float*)d_in[2];
    const float* Su = (const float*)d_in[3];
    const float* Sd = (const float*)d_in[4];
    const float* Eg = (const float*)d_in[5];
    const float* Eu = (const float*)d_in[6];
    const float* Ed = (const float*)d_in[7];
    float* Out = (float*)d_out;

    cudaFuncSetAttribute(k_gateup_m, cudaFuncAttributeMaxDynamicSharedMemorySize, GU_SMEM);
    cudaFuncSetAttribute(k_down_m,   cudaFuncAttributeMaxDynamicSharedMemorySize, DN_SMEM);

    k_zero<<<1, 64>>>();
    k_router<<<TT, 256>>>(X, Wr);
    k_scan<<<1, 64>>>();
    k_assign<<<TT / 256, 256>>>();

    // routed experts (z = 0..63) + shared expert (z = 64) in one launch each
    k_gateup_m<<<dim3(TT / 128, II / 64, EE + 1), 256, GU_SMEM>>>(Sg, Su, Eg, Eu);
    k_down_m<<<dim3(TT / 128, HH / 64, EE + 1), 256, DN_SMEM>>>(Sd, Ed);

    k_combine<<<TT * HH / 4 / 256, 256>>>(Out);
}